// round 10
// baseline (speedup 1.0000x reference)
#include <cuda_runtime.h>
#include <cuda_bf16.h>
#include <math.h>
#include <stdint.h>

typedef unsigned long long ull;

// ---------------------------------------------------------------------------
// Problem dimensions
// ---------------------------------------------------------------------------
#define B_   256
#define T_   256
#define DIN  256
#define H_   1024
#define FC_  512
#define DOUT 24
#define G4   4096
#define KTOT 1280        // H + DIN (fused [h | x_t] contraction)

// Tiling: CTA 128x128, 8 warps (2x4), warp tile 64x32, split-K = 4
#define SK 4
#define KSG (KTOT / SK)            // 320 -> 10 stages of 32
#define KSD (H_ / SK)              // 256 -> 8 stages of 32
#define NSTG (KSG / 32)
#define NSTD (KSD / 32)
#define GCTAS (2 * 32 * SK)        // 256
#define DCTAS (2 * 8 * SK)         // 64
#define NCTAS (GCTAS + DCTAS)      // 320

#define ROWB 80                    // padded row stride in bytes (40 bf16)
#define REG_BYTES 10240            // 128 rows * 80B (one of Ahi/Alo/Bhi/Blo)
#define STG_BYTES 40960            // 4 regions per stage
#define SMEM_BYTES (2 * STG_BYTES) // double buffer: 80 KB dynamic

// ---------------------------------------------------------------------------
// Device scratch (static globals — no allocation allowed)
// ---------------------------------------------------------------------------
static __device__ __align__(16) __nv_bfloat16 g_WgT0[(size_t)G4 * KTOT];  // [n][k] hi
static __device__ __align__(16) __nv_bfloat16 g_WgT1[(size_t)G4 * KTOT];  // [n][k] lo
static __device__ __align__(16) __nv_bfloat16 g_WdT0[(size_t)H_ * H_];
static __device__ __align__(16) __nv_bfloat16 g_WdT1[(size_t)H_ * H_];
static __device__ __align__(16) __nv_bfloat16 g_xs0[(size_t)B_ * T_ * DIN];
static __device__ __align__(16) __nv_bfloat16 g_xs1[(size_t)B_ * T_ * DIN];
static __device__ __align__(16) __nv_bfloat16 g_hs0[(size_t)B_ * H_];
static __device__ __align__(16) __nv_bfloat16 g_hs1[(size_t)B_ * H_];
static __device__ __align__(16) __nv_bfloat16 g_cs0[(size_t)B_ * H_];
static __device__ __align__(16) __nv_bfloat16 g_cs1[(size_t)B_ * H_];
static __device__ float g_gateP[SK][(size_t)B_ * G4];  // split-K partials
static __device__ float g_decP[SK][(size_t)B_ * H_];
static __device__ float g_hf[(size_t)B_ * H_];          // fp32 hidden (in-place)
static __device__ float g_cf[(size_t)B_ * H_];          // fp32 cell (in-place)
static __device__ float g_ball[G4];                     // b_lin + b_extra
static __device__ float g_bd2[H_];                      // bd + b_decomp
static __device__ float g_tmp[(size_t)B_ * FC_];

// ---------------------------------------------------------------------------
// Helpers (baseline PTX only — compiles under .target sm_100)
// ---------------------------------------------------------------------------
__device__ __forceinline__ uint32_t smem_u32(const void* p) {
    uint32_t a;
    asm("{ .reg .u64 t; cvta.to.shared.u64 t, %1; cvt.u32.u64 %0, t; }"
        : "=r"(a) : "l"(p));
    return a;
}
__device__ __forceinline__ void cp16(uint32_t dst, const void* src) {
    asm volatile("cp.async.cg.shared.global [%0], [%1], 16;"
                 :: "r"(dst), "l"(src));
}
#define CP_COMMIT() asm volatile("cp.async.commit_group;")
#define CP_WAIT1()  asm volatile("cp.async.wait_group 1;")
#define CP_WAIT0()  asm volatile("cp.async.wait_group 0;")

__device__ __forceinline__ void ldsm4(uint32_t* r, uint32_t addr) {
    asm volatile("ldmatrix.sync.aligned.m8n8.x4.shared.b16 {%0,%1,%2,%3}, [%4];"
                 : "=r"(r[0]), "=r"(r[1]), "=r"(r[2]), "=r"(r[3]) : "r"(addr));
}
__device__ __forceinline__ void mma16816(float* c, const uint32_t* a,
                                         uint32_t b0, uint32_t b1) {
    asm volatile(
        "mma.sync.aligned.m16n8k16.row.col.f32.bf16.bf16.f32 "
        "{%0,%1,%2,%3}, {%4,%5,%6,%7}, {%8,%9}, {%0,%1,%2,%3};"
        : "+f"(c[0]), "+f"(c[1]), "+f"(c[2]), "+f"(c[3])
        : "r"(a[0]), "r"(a[1]), "r"(a[2]), "r"(a[3]), "r"(b0), "r"(b1));
}
__device__ __forceinline__ float sigm(float x) {
    return 1.0f / (1.0f + expf(-x));
}
__device__ __forceinline__ void bsplit(float v, __nv_bfloat16& hi, __nv_bfloat16& lo) {
    hi = __float2bfloat16(v);
    lo = __float2bfloat16(v - __bfloat162float(hi));
}

// ---------------------------------------------------------------------------
// One-time prep kernels
// ---------------------------------------------------------------------------
__global__ __launch_bounds__(256) void init_state(
    const float* __restrict__ b_lin, const float* __restrict__ b_extra,
    const float* __restrict__ bd, const float* __restrict__ b_decomp)
{
    int i = blockIdx.x * 256 + threadIdx.x;           // 65536 threads
    float4 z = make_float4(0.f, 0.f, 0.f, 0.f);
    *reinterpret_cast<float4*>(&g_hf[(size_t)i * 4]) = z;
    *reinterpret_cast<float4*>(&g_cf[(size_t)i * 4]) = z;
    reinterpret_cast<ull*>(g_hs0)[i] = 0ULL;
    reinterpret_cast<ull*>(g_hs1)[i] = 0ULL;
    reinterpret_cast<ull*>(g_cs0)[i] = 0ULL;
    reinterpret_cast<ull*>(g_cs1)[i] = 0ULL;
    if (i < G4 / 4) {
        float4 a = *reinterpret_cast<const float4*>(&b_lin[i * 4]);
        float4 b = *reinterpret_cast<const float4*>(&b_extra[i * 4]);
        *reinterpret_cast<float4*>(&g_ball[i * 4]) =
            make_float4(a.x + b.x, a.y + b.y, a.z + b.z, a.w + b.w);
    }
    if (i < H_ / 4) {
        float4 a = *reinterpret_cast<const float4*>(&bd[i * 4]);
        float4 b = *reinterpret_cast<const float4*>(&b_decomp[i * 4]);
        *reinterpret_cast<float4*>(&g_bd2[i * 4]) =
            make_float4(a.x + b.x, a.y + b.y, a.z + b.z, a.w + b.w);
    }
}

// transpose [K][N] -> [N][K] with bf16 hi/lo split; gate weights (Ux ‖ Wx)
__global__ void prep_wgate(const float* __restrict__ Ux, const float* __restrict__ Wx)
{
    __shared__ float tile[32][33];
    int tx = threadIdx.x, ty = threadIdx.y;
    int k0 = blockIdx.x * 32, n0 = blockIdx.y * 32;
#pragma unroll
    for (int i = 0; i < 4; i++) {
        int k = k0 + ty + i * 8, n = n0 + tx;
        tile[ty + i * 8][tx] = (k < H_) ? Ux[(size_t)k * G4 + n]
                                        : Wx[(size_t)(k - H_) * G4 + n];
    }
    __syncthreads();
#pragma unroll
    for (int i = 0; i < 4; i++) {
        int n = n0 + ty + i * 8, k = k0 + tx;
        float v = tile[tx][ty + i * 8];
        __nv_bfloat16 hi, lo; bsplit(v, hi, lo);
        g_WgT0[(size_t)n * KTOT + k] = hi;
        g_WgT1[(size_t)n * KTOT + k] = lo;
    }
}

__global__ void prep_wd(const float* __restrict__ Wd)
{
    __shared__ float tile[32][33];
    int tx = threadIdx.x, ty = threadIdx.y;
    int k0 = blockIdx.x * 32, n0 = blockIdx.y * 32;
#pragma unroll
    for (int i = 0; i < 4; i++)
        tile[ty + i * 8][tx] = Wd[(size_t)(k0 + ty + i * 8) * H_ + n0 + tx];
    __syncthreads();
#pragma unroll
    for (int i = 0; i < 4; i++) {
        int n = n0 + ty + i * 8, k = k0 + tx;
        float v = tile[tx][ty + i * 8];
        __nv_bfloat16 hi, lo; bsplit(v, hi, lo);
        g_WdT0[(size_t)n * H_ + k] = hi;
        g_WdT1[(size_t)n * H_ + k] = lo;
    }
}

__global__ __launch_bounds__(256) void prep_x(const float* __restrict__ x)
{
    size_t i = (size_t)(blockIdx.x * 256 + threadIdx.x) * 4;
    float4 v = *reinterpret_cast<const float4*>(&x[i]);
    __nv_bfloat16 h0, l0, h1, l1, h2, l2, h3, l3;
    bsplit(v.x, h0, l0); bsplit(v.y, h1, l1);
    bsplit(v.z, h2, l2); bsplit(v.w, h3, l3);
    __nv_bfloat162 a, b;
    a.x = h0; a.y = h1; b.x = h2; b.y = h3;
    *reinterpret_cast<__nv_bfloat162*>(&g_xs0[i])     = a;
    *reinterpret_cast<__nv_bfloat162*>(&g_xs0[i + 2]) = b;
    a.x = l0; a.y = l1; b.x = l2; b.y = l3;
    *reinterpret_cast<__nv_bfloat162*>(&g_xs1[i])     = a;
    *reinterpret_cast<__nv_bfloat162*>(&g_xs1[i + 2]) = b;
}

// ---------------------------------------------------------------------------
// Per-step tensor-core GEMM via mma.sync (HMMA). 320 CTAs, 256 threads:
//   [0,256):   gates partial [128b x 128n] = [h|x_t](hi/lo) @ WgT(hi/lo)
//   [256,320): decomp partial [128b x 128n] = c(hi/lo) @ WdT(hi/lo)
// 8 warps (2m x 4n), warp tile 64x32. 3-term bf16 split, fp32 accum.
// All ldmatrix for a k16 slice issued up-front, then 48 independent MMAs.
// ---------------------------------------------------------------------------
__global__ __launch_bounds__(256) void step_mma(int t)
{
    extern __shared__ __align__(16) char smem[];
    const uint32_t sbase = smem_u32(smem);

    const int bid = blockIdx.x;
    const bool isg = bid < GCTAS;

    int n0, m0, ks, nst, bstride, ldO;
    const __nv_bfloat16 *Bhi, *Blo;
    float* Out;
    if (isg) {
        int r = bid;
        ks = r & (SK - 1); r >>= 2;
        n0 = (r & 31) * 128; m0 = (r >> 5) * 128;
        nst = NSTG; bstride = KTOT; ldO = G4;
        Bhi = g_WgT0; Blo = g_WgT1; Out = &g_gateP[ks][0];
    } else {
        int r = bid - GCTAS;
        ks = r & (SK - 1); r >>= 2;
        n0 = (r & 7) * 128; m0 = (r >> 3) * 128;
        nst = NSTD; bstride = H_; ldO = H_;
        Bhi = g_WdT0; Blo = g_WdT1; Out = &g_decP[ks][0];
    }
    const int kbase = ks * (isg ? KSG : KSD);
    const __nv_bfloat16* Ahi_s = isg ? g_hs0 : g_cs0;
    const __nv_bfloat16* Alo_s = isg ? g_hs1 : g_cs1;

    const int tid  = threadIdx.x;
    const int lane = tid & 31;
    const int warp = tid >> 5;
    const int wm   = (warp >> 2) * 64;   // 2 m-warps
    const int wn   = (warp & 3) * 32;    // 4 n-warps

    // ldmatrix per-lane byte offsets within a region
    uint32_t aoff[4], boff[2];
#pragma unroll
    for (int mt = 0; mt < 4; mt++)
        aoff[mt] = (uint32_t)((wm + mt * 16 + (lane & 15)) * ROWB +
                              ((lane >> 4) & 1) * 16);
#pragma unroll
    for (int np = 0; np < 2; np++)
        boff[np] = (uint32_t)((wn + np * 16 + (lane & 7) + ((lane >> 4) << 3)) * ROWB +
                              ((lane >> 3) & 1) * 16);

    float acc[4][4][4];   // [mt][n8-frag][quad]
#pragma unroll
    for (int mt = 0; mt < 4; mt++)
#pragma unroll
        for (int nt = 0; nt < 4; nt++)
#pragma unroll
            for (int q = 0; q < 4; q++) acc[mt][nt][q] = 0.f;

    // ---- cp.async stage: Ahi|Alo|Bhi|Blo, 128 rows x 32 k bf16 each ----
    auto stage = [&](int s) {
        const uint32_t sb = sbase + (uint32_t)((s & 1) * STG_BYTES);
        const int k0 = kbase + s * 32;
#pragma unroll
        for (int j = 0; j < 8; j++) {
            const int idx = j * 256 + tid;
            const int w   = idx >> 9;           // region 0..3
            const int rem = idx & 511;
            const int rr  = rem >> 2;
            const int kc  = rem & 3;
            const int kg  = k0 + kc * 8;
            const __nv_bfloat16* src;
            if (w < 2) {
                if (isg && kg >= H_)
                    src = (w ? g_xs1 : g_xs0) +
                          ((size_t)(m0 + rr) * T_ + t) * DIN + (kg - H_);
                else
                    src = (w ? Alo_s : Ahi_s) + (size_t)(m0 + rr) * H_ + kg;
            } else {
                src = ((w == 2) ? Bhi : Blo) + (size_t)(n0 + rr) * bstride + kg;
            }
            cp16(sb + (uint32_t)(w * REG_BYTES + rr * ROWB + kc * 16), src);
        }
        CP_COMMIT();
    };

    stage(0);
    stage(1);
    CP_WAIT1();
    __syncthreads();

    for (int s = 0; ; s++) {
        const uint32_t sb = sbase + (uint32_t)((s & 1) * STG_BYTES);
#pragma unroll
        for (int kk = 0; kk < 2; kk++) {
            const uint32_t kb = sb + kk * 32;   // 16 bf16 = 32B per k16 step
            uint32_t ahif[4][4], alof[4][4], bh[2][4], bl[2][4];
            // all fragment loads up-front (12 ldmatrix)
#pragma unroll
            for (int mt = 0; mt < 4; mt++) {
                ldsm4(ahif[mt], kb + aoff[mt]);
                ldsm4(alof[mt], kb + REG_BYTES + aoff[mt]);
            }
#pragma unroll
            for (int np = 0; np < 2; np++) {
                ldsm4(bh[np], kb + 2 * REG_BYTES + boff[np]);
                ldsm4(bl[np], kb + 3 * REG_BYTES + boff[np]);
            }
            // 48 independent MMAs (3 split terms x 16 tiles)
#pragma unroll
            for (int mt = 0; mt < 4; mt++)
#pragma unroll
                for (int np = 0; np < 2; np++) {
                    mma16816(acc[mt][np * 2],     ahif[mt], bh[np][0], bh[np][1]);
                    mma16816(acc[mt][np * 2 + 1], ahif[mt], bh[np][2], bh[np][3]);
                    mma16816(acc[mt][np * 2],     alof[mt], bh[np][0], bh[np][1]);
                    mma16816(acc[mt][np * 2 + 1], alof[mt], bh[np][2], bh[np][3]);
                    mma16816(acc[mt][np * 2],     ahif[mt], bl[np][0], bl[np][1]);
                    mma16816(acc[mt][np * 2 + 1], ahif[mt], bl[np][2], bl[np][3]);
                }
        }
        if (s + 1 == nst) break;
        __syncthreads();                 // done reading buffer s&1
        if (s + 2 < nst) { stage(s + 2); CP_WAIT1(); }
        else             { CP_WAIT0(); }
        __syncthreads();                 // buffer (s+1)&1 fully staged
    }

    // ---- write split-K partial tile ----
    const int lr  = lane >> 2;
    const int lc2 = (lane & 3) * 2;
#pragma unroll
    for (int mt = 0; mt < 4; mt++) {
#pragma unroll
        for (int nt = 0; nt < 4; nt++) {
            const int row = m0 + wm + mt * 16 + lr;
            const int col = n0 + wn + nt * 8 + lc2;
            *reinterpret_cast<float2*>(&Out[(size_t)row * ldO + col]) =
                make_float2(acc[mt][nt][0], acc[mt][nt][1]);
            *reinterpret_cast<float2*>(&Out[(size_t)(row + 8) * ldO + col]) =
                make_float2(acc[mt][nt][2], acc[mt][nt][3]);
        }
    }
}

// ---------------------------------------------------------------------------
// Per-step epilogue: sum split-K partials, decay decomposition, LSTM gate
// math (fp32 in-place), emit bf16 hi/lo h and c for the next step.
// ---------------------------------------------------------------------------
__global__ __launch_bounds__(256) void step_epi(
    int t, const float* __restrict__ elapsed)   // [B][T]
{
    int idx = blockIdx.x * 256 + threadIdx.x;   // 0..65535
    int b = idx >> 8;
    int n4 = (idx & 255) << 2;

    float dt = elapsed[(size_t)b * T_ + t];
    float Td = 1.0f / logf(dt + 2.7183f);

    float4 dec = make_float4(0.f, 0.f, 0.f, 0.f);
    float4 gi = dec, gf = dec, go = dec, gc = dec;
#pragma unroll
    for (int s = 0; s < SK; s++) {
        float4 d = *reinterpret_cast<const float4*>(&g_decP[s][(size_t)b * H_ + n4]);
        dec.x += d.x; dec.y += d.y; dec.z += d.z; dec.w += d.w;
        const float* grow = &g_gateP[s][(size_t)b * G4];
        float4 a;
        a = *reinterpret_cast<const float4*>(&grow[0 * H_ + n4]);
        gi.x += a.x; gi.y += a.y; gi.z += a.z; gi.w += a.w;
        a = *reinterpret_cast<const float4*>(&grow[1 * H_ + n4]);
        gf.x += a.x; gf.y += a.y; gf.z += a.z; gf.w += a.w;
        a = *reinterpret_cast<const float4*>(&grow[2 * H_ + n4]);
        go.x += a.x; go.y += a.y; go.z += a.z; go.w += a.w;
        a = *reinterpret_cast<const float4*>(&grow[3 * H_ + n4]);
        gc.x += a.x; gc.y += a.y; gc.z += a.z; gc.w += a.w;
    }

    float4 bb  = *reinterpret_cast<const float4*>(&g_bd2[n4]);
    float4 cp4 = *reinterpret_cast<const float4*>(&g_cf[(size_t)b * H_ + n4]);
    float4 bi = *reinterpret_cast<const float4*>(&g_ball[0 * H_ + n4]);
    float4 bf = *reinterpret_cast<const float4*>(&g_ball[1 * H_ + n4]);
    float4 bo = *reinterpret_cast<const float4*>(&g_ball[2 * H_ + n4]);
    float4 bc = *reinterpret_cast<const float4*>(&g_ball[3 * H_ + n4]);

    float cn[4], hn[4];
#define TLSTM_COMP(K, X)                                                  \
    {                                                                     \
        float cst = tanhf(dec.X + bb.X);                                  \
        float cm = cp4.X - cst + Td * cst;                                \
        float c2 = sigm(gf.X + bf.X) * cm +                               \
                   sigm(gi.X + bi.X) * tanhf(gc.X + bc.X);                \
        cn[K] = c2;                                                       \
        hn[K] = sigm(go.X + bo.X) * tanhf(c2);                            \
    }
    TLSTM_COMP(0, x) TLSTM_COMP(1, y) TLSTM_COMP(2, z) TLSTM_COMP(3, w)
#undef TLSTM_COMP

    size_t o = (size_t)b * H_ + n4;
    *reinterpret_cast<float4*>(&g_cf[o]) = make_float4(cn[0], cn[1], cn[2], cn[3]);
    *reinterpret_cast<float4*>(&g_hf[o]) = make_float4(hn[0], hn[1], hn[2], hn[3]);

    __nv_bfloat16 chi[4], clo[4], hhi[4], hlo[4];
#pragma unroll
    for (int k = 0; k < 4; k++) {
        bsplit(cn[k], chi[k], clo[k]);
        bsplit(hn[k], hhi[k], hlo[k]);
    }
    __nv_bfloat162 p;
    p.x = chi[0]; p.y = chi[1]; *reinterpret_cast<__nv_bfloat162*>(&g_cs0[o])     = p;
    p.x = chi[2]; p.y = chi[3]; *reinterpret_cast<__nv_bfloat162*>(&g_cs0[o + 2]) = p;
    p.x = clo[0]; p.y = clo[1]; *reinterpret_cast<__nv_bfloat162*>(&g_cs1[o])     = p;
    p.x = clo[2]; p.y = clo[3]; *reinterpret_cast<__nv_bfloat162*>(&g_cs1[o + 2]) = p;
    p.x = hhi[0]; p.y = hhi[1]; *reinterpret_cast<__nv_bfloat162*>(&g_hs0[o])     = p;
    p.x = hhi[2]; p.y = hhi[3]; *reinterpret_cast<__nv_bfloat162*>(&g_hs0[o + 2]) = p;
    p.x = hlo[0]; p.y = hlo[1]; *reinterpret_cast<__nv_bfloat162*>(&g_hs1[o])     = p;
    p.x = hlo[2]; p.y = hlo[3]; *reinterpret_cast<__nv_bfloat162*>(&g_hs1[o + 2]) = p;
}

// ---------------------------------------------------------------------------
// Output head
// ---------------------------------------------------------------------------
__global__ __launch_bounds__(256) void fc1_kernel(
    const float* __restrict__ w, const float* __restrict__ bias)
{
    int idx = blockIdx.x * 256 + threadIdx.x;  // B*FC
    int b = idx >> 9, n = idx & 511;
    const float* hrow = &g_hf[(size_t)b * H_];
    float acc = bias[n];
#pragma unroll 8
    for (int k = 0; k < H_; k++)
        acc += hrow[k] * w[(size_t)k * FC_ + n];
    g_tmp[idx] = fmaxf(acc, 0.0f);
}

__global__ __launch_bounds__(256) void fco_kernel(
    const float* __restrict__ w, const float* __restrict__ bias,
    float* __restrict__ out)
{
    int idx = blockIdx.x * 256 + threadIdx.x;  // B*DOUT
    if (idx >= B_ * DOUT) return;
    int b = idx / DOUT, n = idx % DOUT;
    const float* trow = &g_tmp[(size_t)b * FC_];
    float acc = bias[n];
#pragma unroll 8
    for (int k = 0; k < FC_; k++)
        acc += trow[k] * w[(size_t)k * DOUT + n];
    out[idx] = acc;
}

// ---------------------------------------------------------------------------
// Launch
// ---------------------------------------------------------------------------
extern "C" void kernel_launch(void* const* d_in, const int* in_sizes, int n_in,
                              void* d_out, int out_size) {
    (void)in_sizes; (void)n_in; (void)out_size;
    const float* x        = (const float*)d_in[0];
    const float* elapsed  = (const float*)d_in[1];
    const float* Wx       = (const float*)d_in[2];
    const float* Ux       = (const float*)d_in[3];
    const float* b_lin    = (const float*)d_in[4];
    const float* b_extra  = (const float*)d_in[5];
    const float* Wd       = (const float*)d_in[6];
    const float* bd       = (const float*)d_in[7];
    const float* b_decomp = (const float*)d_in[8];
    const float* fc1_w    = (const float*)d_in[9];
    const float* fc1_b    = (const float*)d_in[10];
    const float* fco_w    = (const float*)d_in[11];
    const float* fco_b    = (const float*)d_in[12];
    float* out = (float*)d_out;

    static int smem_set = 0;
    if (!smem_set) {
        cudaFuncSetAttribute(step_mma,
                             cudaFuncAttributeMaxDynamicSharedMemorySize,
                             SMEM_BYTES);
        smem_set = 1;
    }

    // one-time prep (inside graph; deterministic per call)
    init_state<<<256, 256>>>(b_lin, b_extra, bd, b_decomp);
    prep_wgate<<<dim3(KTOT / 32, G4 / 32), dim3(32, 8)>>>(Ux, Wx);
    prep_wd<<<dim3(H_ / 32, H_ / 32), dim3(32, 8)>>>(Wd);
    prep_x<<<(B_ * T_ * DIN / 4) / 256, 256>>>(x);

    // sequential recurrence: HMMA GEMM + elementwise epilogue per step
    for (int t = 0; t < T_; t++) {
        step_mma<<<NCTAS, 256, SMEM_BYTES>>>(t);
        step_epi<<<256, 256>>>(t, elapsed);
    }

    fc1_kernel<<<(B_ * FC_) / 256, 256>>>(fc1_w, fc1_b);
    fco_kernel<<<(B_ * DOUT + 255) / 256, 256>>>(fco_w, fco_b, out);
}